// round 17
// baseline (speedup 1.0000x reference)
#include <cuda_runtime.h>
#include <cuda_bf16.h>
#include <cuda_fp16.h>
#include <mma.h>
#include <math.h>
#include <cstdint>

using namespace nvcuda;

// Problem constants (fixed by the dataset)
#define BATCH 8
#define SEQ   2048
#define HDIM  4096
#define DDIM  128
#define NSENT 128

// split-K for the HMMA GEMM
#define KS2   16
#define KSL   (HDIM / KS2)     // 256 fp32 k per CTA
#define STG   64               // k per stage
#define NSTG  (KSL / STG)      // 4 mma-stages (single fp16 term)
#define MMA_THREADS 256        // 8 warps; CTA tile M=64 x N=128
#define MROWS 64               // sentence rows per CTA (M-split x2)

// split-K for the q/v GEMVs
#define QSPL  8
#define QSEG  (HDIM / QSPL)    // 512 floats per warp segment

#define TSTRIDE 72                       // fp16 tile row stride (144B)
#define ATILE_H (MROWS * TSTRIDE * 2)    // 9216 B per A fp16 stage tile
#define A_TOTAL (NSTG * ATILE_H)         // 36864 B (all 4 stages resident)
#define WTILE_H (128 * TSTRIDE * 2)      // 18432 B per W fp16 stage tile
#define WBUFS   3
#define MMA_SMEM_TOTAL (A_TOTAL + WBUFS * WTILE_H)   // 92160 B -> 2 CTAs/SM

// ---------------- scratch (no allocations allowed) ----------------
__device__ int   g_idx[BATCH * NSENT];
__device__ float g_qpart[QSPL * BATCH * DDIM];               // 32 KB
__device__ float g_vpart[QSPL * BATCH * NSENT];              // 32 KB
__device__ float g_part[(size_t)KS2 * BATCH * NSENT * DDIM]; // 8 MB fp32 partials
__device__ float g_kf [(size_t)BATCH * NSENT * DDIM];        // 512 KB (RoPE'd K)
__device__ __half g_Whf[(size_t)DDIM * HDIM];                // 1 MB  fp16(W)
__device__ int   g_cnt1[BATCH];                              // split-arrival counters
__device__ int   g_cnt2[BATCH];                              // kred-done counters

// ---------------- PTX helpers (baseline compute_103 only!) ----------------
__device__ __forceinline__ uint32_t smem_u32(const void* p) {
    uint32_t a;
    asm("{ .reg .u64 t; cvta.to.shared.u64 t, %1; cvt.u32.u64 %0, t; }" : "=r"(a) : "l"(p));
    return a;
}
__device__ __forceinline__ void cp_async16(uint32_t saddr, const void* g) {
    asm volatile("cp.async.cg.shared.global [%0], [%1], 16;" :: "r"(saddr), "l"(g));
}
#define CP_COMMIT() asm volatile("cp.async.commit_group;" ::: "memory")
#define CP_WAIT(n)  asm volatile("cp.async.wait_group %0;" :: "n"(n) : "memory")

// ---------------- kernel A: fused idx + counter reset + W fp16 convert ----
__global__ __launch_bounds__(256) void prep_kernel(const int* __restrict__ mask,
                                                   const float* __restrict__ Wk) {
    if (blockIdx.x < BATCH) {
        if (blockIdx.x == 0 && threadIdx.x < BATCH) {     // reset sync counters
            g_cnt1[threadIdx.x] = 0;
            g_cnt2[threadIdx.x] = 0;
        }
        // sentence-position extraction, MLP-64, warp 0 only
        if (threadIdx.x >= 32) return;
        int b = blockIdx.x;
        int lane = threadIdx.x;
        const int4* row = (const int4*)(mask + (size_t)b * SEQ);
        int4 v[16];
#pragma unroll
        for (int i = 0; i < 16; i++) v[i] = row[i * 32 + lane];
        unsigned lt = (1u << lane) - 1u;
        int count = 0;
#pragma unroll
        for (int i = 0; i < 16; i++) {
            unsigned b0 = __ballot_sync(0xffffffffu, v[i].x != 0);
            unsigned b1 = __ballot_sync(0xffffffffu, v[i].y != 0);
            unsigned b2 = __ballot_sync(0xffffffffu, v[i].z != 0);
            unsigned b3 = __ballot_sync(0xffffffffu, v[i].w != 0);
            int prel = __popc(b0 & lt) + __popc(b1 & lt) + __popc(b2 & lt) + __popc(b3 & lt);
            int basepos = i * 128 + lane * 4;
            int slot = count + prel;
            if (v[i].x) { if (slot < NSENT) g_idx[b * NSENT + slot] = basepos + 0; slot++; }
            if (v[i].y) { if (slot < NSENT) g_idx[b * NSENT + slot] = basepos + 1; slot++; }
            if (v[i].z) { if (slot < NSENT) g_idx[b * NSENT + slot] = basepos + 2; slot++; }
            if (v[i].w) { if (slot < NSENT) g_idx[b * NSENT + slot] = basepos + 3; slot++; }
            count += __popc(b0) + __popc(b1) + __popc(b2) + __popc(b3);
        }
        return;
    }
    // W fp16 convert
    int i = (blockIdx.x - BATCH) * 256 + threadIdx.x;   // over DDIM*HDIM/4
    if (i >= DDIM * HDIM / 4) return;
    float4 x = ((const float4*)Wk)[i];
    __half2 h0 = __floats2half2_rn(x.x, x.y);
    __half2 h1 = __floats2half2_rn(x.z, x.w);
    uint2 hv; hv.x = *(uint32_t*)&h0; hv.y = *(uint32_t*)&h1;
    ((uint2*)g_Whf)[i] = hv;
}

// ---------------- kernel B: q + v GEMVs, split-K x8 (warp per partial) --
__global__ __launch_bounds__(256) void qv_kernel(
    const float* __restrict__ hidden,
    const float* __restrict__ Wq, const float* __restrict__ Wr)
{
    int gw = blockIdx.x * 8 + (threadIdx.x >> 5);   // 0..16383
    int lane = threadIdx.x & 31;
    int sp   = gw & (QSPL - 1);
    int task = gw >> 3;                 // 0..2047
    const float4* x4;
    const float4* w4;
    if (task < BATCH * DDIM) {          // q task
        int b = task >> 7, d = task & 127;
        int row = g_idx[b * NSENT + NSENT - 1];
        x4 = (const float4*)(hidden + ((size_t)b * SEQ + row) * HDIM + sp * QSEG);
        w4 = (const float4*)(Wq + (size_t)d * HDIM + sp * QSEG);
    } else {                            // v task
        int tt = task - BATCH * DDIM;
        int b = tt >> 7, i = tt & 127;
        int row = g_idx[b * NSENT + i];
        x4 = (const float4*)(hidden + ((size_t)b * SEQ + row) * HDIM + sp * QSEG);
        w4 = (const float4*)(Wr + sp * QSEG);
    }
    float4 xa[4], wa[4];
#pragma unroll
    for (int it = 0; it < 4; it++) {    // all 8 LDG.128 in flight
        xa[it] = x4[it * 32 + lane];
        wa[it] = w4[it * 32 + lane];
    }
    float s = 0.f;
#pragma unroll
    for (int it = 0; it < 4; it++)
        s += xa[it].x * wa[it].x + xa[it].y * wa[it].y
           + xa[it].z * wa[it].z + xa[it].w * wa[it].w;
#pragma unroll
    for (int o = 16; o > 0; o >>= 1) s += __shfl_xor_sync(0xffffffffu, s, o);
    if (lane == 0) {
        if (task < BATCH * DDIM) g_qpart[sp * (BATCH * DDIM) + task] = s;
        else g_vpart[sp * (BATCH * NSENT) + task - BATCH * DDIM] = s;
    }
}

// ---------------- kernel C: fused GEMM + split-K reduce/RoPE + finalize ---
// grid (KS2, 2*BATCH) = 256 CTAs, all co-resident (2/SM) -> spin-safe.
// Phase 1: single-term fp16 WMMA (as R16). Phase 2: per-batch cooperative
// kred after cnt1[b]==32. Phase 3: CTA (sp0,mh0) of each batch runs
// attention+rewards after cnt2[b]==32.
__global__ void __launch_bounds__(MMA_THREADS, 2)
mma_kernel(const float* __restrict__ hidden,
           const float* __restrict__ bk,
           const float* __restrict__ bq,
           const float* __restrict__ br,
           float* __restrict__ out)
{
    extern __shared__ char smem[];
    __shared__ int idx_sh[MROWS];
    __shared__ float qfull[DDIM];
    __shared__ float qsh[DDIM];
    __shared__ float red[NSENT];
    __shared__ float vsh[NSENT];

    int t  = threadIdx.x;
    int sp = blockIdx.x;
    int b  = blockIdx.y >> 1, mh = blockIdx.y & 1;
    int wid = t >> 5;
    int warp_m = wid & 1;      // 0..1 -> m base = warp_m*32
    int warp_n = wid >> 1;     // 0..3 -> n base = warp_n*32

    const int k0 = sp * KSL;
    if (t < MROWS) idx_sh[t] = g_idx[b * NSENT + mh * MROWS + t];
    __syncthreads();

    // per-thread A chunk addressing: 1024 float4 chunks / 256 threads = 4
    const float* aptr[4];
    int soff[4];
#pragma unroll
    for (int i = 0; i < 4; i++) {
        int lin = t + MMA_THREADS * i;
        int row = lin >> 4, c4 = lin & 15;
        aptr[i] = hidden + ((size_t)b * SEQ + idx_sh[row]) * HDIM + c4 * 4;
        soff[i] = row * TSTRIDE + c4 * 4;     // fp16 element offset in tile
    }

    auto issueW = [&](int j) {            // j = mma-stage 0..3
        int kk = k0 + j * STG;
        char* wt = smem + A_TOTAL + (j % WBUFS) * WTILE_H;
#pragma unroll
        for (int i = 0; i < 4; i++) {     // 1024 16B chunks (128 rows x 8)
            int lin = t + MMA_THREADS * i;
            int row = lin >> 3, ch = lin & 7;
            cp_async16(smem_u32(wt + row * (TSTRIDE * 2) + ch * 16),
                       g_Whf + (size_t)row * HDIM + kk + ch * 8);
        }
        CP_COMMIT();
    };
    auto loadA = [&](int s, float4* r) {
        int kk = k0 + s * STG;
#pragma unroll
        for (int i = 0; i < 4; i++) r[i] = *(const float4*)(aptr[i] + kk);
    };
    auto convertA = [&](int s, const float4* r) {   // fp32 regs -> fp16 tile s
        __half* At = (__half*)(smem + s * ATILE_H);
#pragma unroll
        for (int i = 0; i < 4; i++) {
            __half2 h01 = __floats2half2_rn(r[i].x, r[i].y);
            __half2 h23 = __floats2half2_rn(r[i].z, r[i].w);
            uint2 hv; hv.x = *(uint32_t*)&h01; hv.y = *(uint32_t*)&h23;
            *(uint2*)(At + soff[i]) = hv;
        }
    };

    wmma::fragment<wmma::accumulator, 16, 16, 16, float> acc[2][2];
#pragma unroll
    for (int i = 0; i < 2; i++)
#pragma unroll
        for (int j = 0; j < 2; j++) wmma::fill_fragment(acc[i][j], 0.0f);

    // prologue: W0..W2 in flight; gather+convert all 4 A stages (2-deep)
    issueW(0); issueW(1); issueW(2);
    {
        float4 ra[4], rb[4];
        loadA(0, ra); loadA(1, rb);
        convertA(0, ra); loadA(2, ra);
        convertA(1, rb); loadA(3, rb);
        convertA(2, ra);
        convertA(3, rb);
    }
    __syncthreads();     // A tiles visible to all warps

#pragma unroll
    for (int j = 0; j < NSTG; j++) {
        if (j <= 1)      { CP_WAIT(2); }   // W(j) complete
        else if (j == 2) { CP_WAIT(1); }
        else             { CP_WAIT(0); }
        __syncthreads();                   // W(j) visible CTA-wide

        const __half* At = (const __half*)(smem + j * ATILE_H);
        const __half* Wt = (const __half*)(smem + A_TOTAL + (j % WBUFS) * WTILE_H);
        const __half* Ab = At + warp_m * 32 * TSTRIDE;
        const __half* Wb = Wt + warp_n * 32 * TSTRIDE;

#pragma unroll
        for (int kk = 0; kk < STG / 16; kk++) {
            wmma::fragment<wmma::matrix_a, 16, 16, 16, __half, wmma::row_major> ah[2];
            wmma::fragment<wmma::matrix_b, 16, 16, 16, __half, wmma::col_major> wf[2];
#pragma unroll
            for (int i = 0; i < 2; i++)
                wmma::load_matrix_sync(ah[i], Ab + i * 16 * TSTRIDE + kk * 16, TSTRIDE);
#pragma unroll
            for (int jn = 0; jn < 2; jn++)
                wmma::load_matrix_sync(wf[jn], Wb + jn * 16 * TSTRIDE + kk * 16, TSTRIDE);
#pragma unroll
            for (int i = 0; i < 2; i++)
#pragma unroll
                for (int jn = 0; jn < 2; jn++)
                    wmma::mma_sync(acc[i][jn], ah[i], wf[jn], acc[i][jn]);
        }

        __syncthreads();                  // all warps done reading W buf
        if (j + WBUFS < NSTG) issueW(j + WBUFS);
    }

    // ---- epilogue: store split-K partial (this CTA's 64-row half) ----
    float* po = g_part + (((size_t)(sp * BATCH + b)) << 14) + (size_t)mh * MROWS * DDIM;
#pragma unroll
    for (int i = 0; i < 2; i++)
#pragma unroll
        for (int jn = 0; jn < 2; jn++)
            wmma::store_matrix_sync(po + (size_t)(warp_m * 32 + i * 16) * DDIM
                                       + warp_n * 32 + jn * 16,
                                    acc[i][jn], DDIM, wmma::mem_row_major);

    // ================= phase 2: cooperative split-K reduce + RoPE =========
    __threadfence();
    __syncthreads();
    if (t == 0) {
        atomicAdd(&g_cnt1[b], 1);
        while (atomicAdd(&g_cnt1[b], 0) < 2 * KS2) { }   // all 32 CTAs of batch b
    }
    __syncthreads();

    {
        int chunk = sp * 2 + mh;              // 0..31
        if (t < 128) {
            int q  = chunk * 128 + t;         // quad within batch, 0..4095
            int jq = q & 31;                  // quad: pairs 2jq, 2jq+1
            int ts = (q >> 5) & 127;          // sentence index
            float4 s = ((const float4*)bk)[jq];
#pragma unroll
            for (int sp2 = 0; sp2 < KS2; sp2++) {
                float4 v = ((const float4*)g_part)[(((size_t)(sp2 * BATCH + b)) << 12) + q];
                s.x += v.x; s.y += v.y; s.z += v.z; s.w += v.w;
            }
            const float c = 0.20762050593045163f;   // log2(1e4)/64
            float f0 = exp2f(-(float)(2 * jq) * c);
            float f1 = exp2f(-(float)(2 * jq + 1) * c);
            float sn0, cs0, sn1, cs1;
            sincosf((float)ts * f0, &sn0, &cs0);
            sincosf((float)ts * f1, &sn1, &cs1);
            float4 o;
            o.x = s.x * cs0 - s.y * sn0;
            o.y = s.x * sn0 + s.y * cs0;
            o.z = s.z * cs1 - s.w * sn1;
            o.w = s.z * sn1 + s.w * cs1;
            ((float4*)g_kf)[b * 4096 + q] = o;
        }
    }
    __threadfence();
    __syncthreads();
    if (t == 0) atomicAdd(&g_cnt2[b], 1);

    // ================= phase 3: finalize (one CTA per batch) ==============
    if (sp != 0 || mh != 0) return;
    if (t == 0) {
        while (atomicAdd(&g_cnt2[b], 0) < 2 * KS2) { }
    }
    __syncthreads();

    const double LN1E4   = 9.210340371976184;
    const double INV_2PI = 0.15915494309189535;
    const double TWO_PI  = 6.283185307179586;

    if (t < NSENT) {
        float v = br[0];
#pragma unroll
        for (int sp2 = 0; sp2 < QSPL; sp2++)
            v += g_vpart[sp2 * (BATCH * NSENT) + b * NSENT + t];
        vsh[t] = v;
        float qv = bq[t];
#pragma unroll
        for (int sp2 = 0; sp2 < QSPL; sp2++)
            qv += g_qpart[sp2 * (BATCH * DDIM) + b * DDIM + t];
        qfull[t] = qv;
    }
    __syncthreads();

    if (t < DDIM / 2) {
        double f   = exp(-((double)(2 * t) / (double)DDIM) * LN1E4);
        double ang = (double)(NSENT - 1) * f;
        double kk  = rint(ang * INV_2PI);
        float  ar  = (float)(ang - kk * TWO_PI);
        float c, sn; sincosf(ar, &sn, &c);
        float re = qfull[2 * t], im = qfull[2 * t + 1];
        const float isd = 0.08838834764831845f;    // 1/sqrt(128)
        qsh[2 * t]     = (re * c - im * sn) * isd;
        qsh[2 * t + 1] = (re * sn + im * c) * isd;
    }
    __syncthreads();

    float logit = 0.f;
    if (t < NSENT) {
        const float4* krow = (const float4*)(g_kf + ((size_t)b << 14) + (size_t)t * DDIM);
        const float4* q4   = (const float4*)qsh;
#pragma unroll
        for (int j = 0; j < DDIM / 4; j++) {
            float4 k4 = krow[j], qq = q4[j];
            logit += k4.x * qq.x + k4.y * qq.y + k4.z * qq.z + k4.w * qq.w;
        }
        red[t] = logit;
    }
    __syncthreads();
#pragma unroll
    for (int o = 64; o > 0; o >>= 1) { if (t < o) red[t] = fmaxf(red[t], red[t + o]); __syncthreads(); }
    float mx = red[0]; __syncthreads();
    float e = 0.f;
    if (t < NSENT) { e = expf(logit - mx); red[t] = e; }
    __syncthreads();
#pragma unroll
    for (int o = 64; o > 0; o >>= 1) { if (t < o) red[t] += red[t + o]; __syncthreads(); }
    float ssum = red[0]; __syncthreads();

    if (t < NSENT) {
        float attn = e / ssum;
        float v  = vsh[t];
        float sr = (t == 0) ? v : (v - vsh[t - 1]);
        float srw = sr * attn;
        out[b * NSENT + t] = srw;
        red[t] = srw;
    }
    __syncthreads();
#pragma unroll
    for (int o = 64; o > 0; o >>= 1) { if (t < o) red[t] += red[t + o]; __syncthreads(); }
    if (t == 0) out[BATCH * NSENT + b] = red[0];
}

// ---------------- host launcher: 3 graph nodes ----------------
extern "C" void kernel_launch(void* const* d_in, const int* in_sizes, int n_in,
                              void* d_out, int out_size) {
    const float* hidden = (const float*)d_in[0];
    const int*   mask   = (const int*)d_in[1];
    int off = (n_in > 2 && in_sizes[2] == 1) ? 3 : 2;
    const float* Wq = (const float*)d_in[off + 0];
    const float* bq = (const float*)d_in[off + 1];
    const float* Wk = (const float*)d_in[off + 2];
    const float* bk = (const float*)d_in[off + 3];
    const float* Wr = (const float*)d_in[off + 4];
    const float* br = (const float*)d_in[off + 5];
    float* out = (float*)d_out;

    cudaFuncSetAttribute(mma_kernel, cudaFuncAttributeMaxDynamicSharedMemorySize,
                         MMA_SMEM_TOTAL);

    prep_kernel<<<BATCH + DDIM * HDIM / 4 / 256, 256>>>(mask, Wk);
    qv_kernel<<<QSPL * 2 * BATCH * NSENT / 8, 256>>>(hidden, Wq, Wr);
    mma_kernel<<<dim3(KS2, 2 * BATCH), MMA_THREADS, MMA_SMEM_TOTAL>>>(hidden, bk, bq, br, out);
    (void)in_sizes; (void)n_in; (void)out_size;
}